// round 1
// baseline (speedup 1.0000x reference)
#include <cuda_runtime.h>
#include <cuda_bf16.h>

#define B_ROWS 8192
#define ITEM_NUM 10000
#define THREADS 256

// Scratch for per-row losses (no cudaMalloc allowed).
__device__ float g_row_loss[B_ROWS];

__global__ __launch_bounds__(THREADS)
void dq_row_kernel(const float* __restrict__ hs,
                   const float* __restrict__ tq,
                   const float* __restrict__ rewards,
                   const float* __restrict__ discount,
                   const unsigned char* __restrict__ is_done,
                   const float* __restrict__ W,
                   const float* __restrict__ bias) {
    const int row = blockIdx.x;
    const float4* __restrict__ hsr = reinterpret_cast<const float4*>(hs + (size_t)row * ITEM_NUM);
    const float4* __restrict__ tqr = reinterpret_cast<const float4*>(tq + (size_t)row * ITEM_NUM);
    const float4* __restrict__ w4  = reinterpret_cast<const float4*>(W);
    const int n4 = ITEM_NUM / 4;  // 2500

    float qs = 0.0f, ns = 0.0f;
    for (int i = threadIdx.x; i < n4; i += THREADS) {
        float4 w = w4[i];
        float4 h = hsr[i];
        float4 t = tqr[i];
        qs = fmaf(h.x, w.x, qs); qs = fmaf(h.y, w.y, qs);
        qs = fmaf(h.z, w.z, qs); qs = fmaf(h.w, w.w, qs);
        ns = fmaf(t.x, w.x, ns); ns = fmaf(t.y, w.y, ns);
        ns = fmaf(t.z, w.z, ns); ns = fmaf(t.w, w.w, ns);
    }

    // Warp reduce both sums
    #pragma unroll
    for (int off = 16; off > 0; off >>= 1) {
        qs += __shfl_down_sync(0xFFFFFFFFu, qs, off);
        ns += __shfl_down_sync(0xFFFFFFFFu, ns, off);
    }

    __shared__ float sq[THREADS / 32];
    __shared__ float sn[THREADS / 32];
    const int lane = threadIdx.x & 31;
    const int wid  = threadIdx.x >> 5;
    if (lane == 0) { sq[wid] = qs; sn[wid] = ns; }
    __syncthreads();

    if (threadIdx.x == 0) {
        float q = 0.0f, n = 0.0f;
        #pragma unroll
        for (int w = 0; w < THREADS / 32; w++) { q += sq[w]; n += sn[w]; }
        const float b = bias[0];
        const float qv  = fmaxf(q + b, 0.0f);
        const float nqv = fmaxf(n + b, 0.0f);
        const float ps  = fabsf(rewards[row] + discount[0] * nqv - qv);
        g_row_loss[row] = is_done[row] ? 0.0f : ps;
    }
}

__global__ __launch_bounds__(1024)
void dq_reduce_kernel(float* __restrict__ out) {
    __shared__ float s[1024];
    float sum = 0.0f;
    // Fixed summation order -> deterministic.
    for (int i = threadIdx.x; i < B_ROWS; i += 1024)
        sum += g_row_loss[i];
    s[threadIdx.x] = sum;
    __syncthreads();
    #pragma unroll
    for (int st = 512; st > 0; st >>= 1) {
        if (threadIdx.x < st) s[threadIdx.x] += s[threadIdx.x + st];
        __syncthreads();
    }
    if (threadIdx.x == 0) out[0] = s[0] / (float)B_ROWS;
}

extern "C" void kernel_launch(void* const* d_in, const int* in_sizes, int n_in,
                              void* d_out, int out_size) {
    const float*         hs       = (const float*)d_in[0];
    // d_in[1] = actions (unused by reference)
    const float*         rewards  = (const float*)d_in[2];
    const float*         discount = (const float*)d_in[3];
    const float*         tq       = (const float*)d_in[4];
    const unsigned char* is_done  = (const unsigned char*)d_in[5];
    const float*         W        = (const float*)d_in[6];
    const float*         bias     = (const float*)d_in[7];
    float* out = (float*)d_out;

    dq_row_kernel<<<B_ROWS, THREADS>>>(hs, tq, rewards, discount, is_done, W, bias);
    dq_reduce_kernel<<<1, 1024>>>(out);
}

// round 3
// speedup vs baseline: 1.0203x; 1.0203x over previous
#include <cuda_runtime.h>
#include <cuda_bf16.h>

#define B_ROWS 8192
#define ITEM_NUM 10000
#define THREADS 256

// Scratch (no cudaMalloc allowed).
__device__ float g_row_loss[B_ROWS];
__device__ unsigned int g_arrived = 0;   // reset by the last block each launch

__global__ __launch_bounds__(THREADS)
void dq_fused_kernel(const float* __restrict__ hs,
                     const float* __restrict__ tq,
                     const float* __restrict__ rewards,
                     const float* __restrict__ discount,
                     const unsigned char* __restrict__ is_done,
                     const float* __restrict__ W,
                     const float* __restrict__ bias,
                     float* __restrict__ out) {
    const int row = blockIdx.x;
    const float4* __restrict__ hsr = reinterpret_cast<const float4*>(hs + (size_t)row * ITEM_NUM);
    const float4* __restrict__ tqr = reinterpret_cast<const float4*>(tq + (size_t)row * ITEM_NUM);
    const float4* __restrict__ w4  = reinterpret_cast<const float4*>(W);
    const int n4 = ITEM_NUM / 4;  // 2500

    float qs = 0.0f, ns = 0.0f;
    for (int i = threadIdx.x; i < n4; i += THREADS) {
        float4 w = w4[i];
        float4 h = hsr[i];
        float4 t = tqr[i];
        qs = fmaf(h.x, w.x, qs); qs = fmaf(h.y, w.y, qs);
        qs = fmaf(h.z, w.z, qs); qs = fmaf(h.w, w.w, qs);
        ns = fmaf(t.x, w.x, ns); ns = fmaf(t.y, w.y, ns);
        ns = fmaf(t.z, w.z, ns); ns = fmaf(t.w, w.w, ns);
    }

    // Warp reduce both sums
    #pragma unroll
    for (int off = 16; off > 0; off >>= 1) {
        qs += __shfl_down_sync(0xFFFFFFFFu, qs, off);
        ns += __shfl_down_sync(0xFFFFFFFFu, ns, off);
    }

    __shared__ float sq[THREADS / 32];
    __shared__ float sn[THREADS / 32];
    __shared__ bool  s_is_last;
    const int lane = threadIdx.x & 31;
    const int wid  = threadIdx.x >> 5;
    if (lane == 0) { sq[wid] = qs; sn[wid] = ns; }
    __syncthreads();

    if (threadIdx.x == 0) {
        float q = 0.0f, n = 0.0f;
        #pragma unroll
        for (int w = 0; w < THREADS / 32; w++) { q += sq[w]; n += sn[w]; }
        const float b = bias[0];
        const float qv  = fmaxf(q + b, 0.0f);
        const float nqv = fmaxf(n + b, 0.0f);
        const float ps  = fabsf(rewards[row] + discount[0] * nqv - qv);
        g_row_loss[row] = is_done[row] ? 0.0f : ps;
        // Publish our row loss, then arrive.
        __threadfence();
        unsigned int prev = atomicAdd(&g_arrived, 1u);
        s_is_last = (prev == (unsigned int)(gridDim.x - 1));
    }
    __syncthreads();

    if (s_is_last) {
        // Last block: deterministic fixed-order reduction of all rows.
        __shared__ float s[THREADS];
        float sum = 0.0f;
        for (int i = threadIdx.x; i < B_ROWS; i += THREADS)
            sum += g_row_loss[i];
        s[threadIdx.x] = sum;
        __syncthreads();
        #pragma unroll
        for (int st = THREADS / 2; st > 0; st >>= 1) {
            if (threadIdx.x < st) s[threadIdx.x] += s[threadIdx.x + st];
            __syncthreads();
        }
        if (threadIdx.x == 0) {
            out[0] = s[0] / (float)B_ROWS;
            g_arrived = 0;  // reset for next graph replay
        }
    }
}

extern "C" void kernel_launch(void* const* d_in, const int* in_sizes, int n_in,
                              void* d_out, int out_size) {
    const float*         hs       = (const float*)d_in[0];
    // d_in[1] = actions (unused by reference)
    const float*         rewards  = (const float*)d_in[2];
    const float*         discount = (const float*)d_in[3];
    const float*         tq       = (const float*)d_in[4];
    const unsigned char* is_done  = (const unsigned char*)d_in[5];
    const float*         W        = (const float*)d_in[6];
    const float*         bias     = (const float*)d_in[7];
    float* out = (float*)d_out;

    dq_fused_kernel<<<B_ROWS, THREADS>>>(hs, tq, rewards, discount, is_done, W, bias, out);
}